// round 1
// baseline (speedup 1.0000x reference)
#include <cuda_runtime.h>

#define N_NODES 50000
#define N_EDGES 800000
#define C 128
#define OUTC 64
#define BN_EPS 1e-5f

// ---------------- scratch (no allocations allowed) ----------------
__device__ int   g_off[N_NODES + 1];
__device__ int   g_cursor[N_NODES];
__device__ int   g_srcs[N_EDGES];
__device__ float g_ws[N_EDGES];
__device__ float g_agg[N_NODES * C];
__device__ float g_h[N_NODES * C];
__device__ float g_x1[N_NODES * C];
__device__ float g_x2[N_NODES * C];
__device__ float g_sum[C];
__device__ float g_sumsq[C];
__device__ float g_scale[C];
__device__ float g_shift[C];

// ---------------- CSR build ----------------
__global__ void zero_deg_kernel() {
    int i = blockIdx.x * blockDim.x + threadIdx.x;
    if (i <= N_NODES) g_off[i] = 0;
}

__global__ void hist_kernel(const int* __restrict__ dst) {
    int e = blockIdx.x * blockDim.x + threadIdx.x;
    if (e < N_EDGES) atomicAdd(&g_off[dst[e]], 1);
}

// single-block scan: counts (in g_off) -> exclusive offsets (in-place) + cursor copy
__global__ void scan_kernel() {
    __shared__ int warp_sums[32];
    __shared__ int carry;
    const int tid = threadIdx.x;
    const int lane = tid & 31;
    const int wid = tid >> 5;
    if (tid == 0) carry = 0;
    __syncthreads();
    for (int base = 0; base < N_NODES; base += 1024) {
        int i = base + tid;
        int v = (i < N_NODES) ? g_off[i] : 0;
        int x = v;
        #pragma unroll
        for (int s = 1; s < 32; s <<= 1) {
            int t = __shfl_up_sync(0xFFFFFFFFu, x, s);
            if (lane >= s) x += t;
        }
        if (lane == 31) warp_sums[wid] = x;
        __syncthreads();
        if (wid == 0) {
            int ws = warp_sums[lane];
            #pragma unroll
            for (int s = 1; s < 32; s <<= 1) {
                int t = __shfl_up_sync(0xFFFFFFFFu, ws, s);
                if (lane >= s) ws += t;
            }
            warp_sums[lane] = ws;
        }
        __syncthreads();
        int warp_prefix = (wid > 0) ? warp_sums[wid - 1] : 0;
        int excl = x + warp_prefix + carry - v;
        if (i < N_NODES) { g_off[i] = excl; g_cursor[i] = excl; }
        __syncthreads();
        if (tid == 0) carry += warp_sums[31];
        __syncthreads();
    }
    if (tid == 0) g_off[N_NODES] = carry;
}

__global__ void build_csr_kernel(const int* __restrict__ src,
                                 const int* __restrict__ dst,
                                 const float* __restrict__ w) {
    int e = blockIdx.x * blockDim.x + threadIdx.x;
    if (e < N_EDGES) {
        int d = dst[e];
        int p = atomicAdd(&g_cursor[d], 1);
        g_srcs[p] = src[e];
        g_ws[p] = w[e];
    }
}

// ---------------- aggregation: one warp per destination node ----------------
__global__ void aggregate_kernel(const float* __restrict__ x, float* __restrict__ agg) {
    int gw = (blockIdx.x * blockDim.x + threadIdx.x) >> 5;
    int lane = threadIdx.x & 31;
    if (gw >= N_NODES) return;
    int j = g_off[gw];
    int e = g_off[gw + 1];
    float4 acc = make_float4(0.f, 0.f, 0.f, 0.f);
    for (; j < e; j++) {
        int s = g_srcs[j];
        float w = g_ws[j];
        float4 v = __ldg((const float4*)(x + (size_t)s * C) + lane);
        acc.x = fmaf(w, v.x, acc.x);
        acc.y = fmaf(w, v.y, acc.y);
        acc.z = fmaf(w, v.z, acc.z);
        acc.w = fmaf(w, v.w, acc.w);
    }
    ((float4*)(agg + (size_t)gw * C))[lane] = acc;
}

// ---------------- fused dual GEMM: H = A0 @ W0 + A1 @ W1 (+bias) ----------------
// A0, A1: [N_NODES, 128] row-major. W0, W1: [128, BN] row-major. H: [N_NODES, BN].
template <int BN>
__global__ void __launch_bounds__(256, 2) gemm_dual_kernel(
    const float* __restrict__ A0, const float* __restrict__ A1,
    const float* __restrict__ W0, const float* __restrict__ W1,
    const float* __restrict__ bias, float* __restrict__ H) {
    constexpr int BM = 128, BK = 16, TM = 8;
    constexpr int TN = BN / 16;
    __shared__ float sA0[BK][BM];
    __shared__ float sA1[BK][BM];
    __shared__ float sW0[BK][BN];
    __shared__ float sW1[BK][BN];

    const int tid = threadIdx.x;
    const int tx = tid & 15;   // 0..15 -> col group
    const int ty = tid >> 4;   // 0..15 -> row group
    const int m0 = blockIdx.x * BM;

    float acc[TM][TN];
    #pragma unroll
    for (int i = 0; i < TM; i++)
        #pragma unroll
        for (int j = 0; j < TN; j++) acc[i][j] = 0.f;

    const int ar = tid >> 2;          // 0..63
    const int ak = (tid & 3) << 2;    // 0,4,8,12
    constexpr int WIT = (BK * BN / 4) / 256;  // 2 for BN=128, 1 for BN=64

    for (int k0 = 0; k0 < C; k0 += BK) {
        // load A tiles (transposed to [k][m])
        #pragma unroll
        for (int r = 0; r < 2; r++) {
            int row = ar + r * 64;
            int gm = m0 + row;
            float4 v0 = make_float4(0.f, 0.f, 0.f, 0.f);
            float4 v1 = make_float4(0.f, 0.f, 0.f, 0.f);
            if (gm < N_NODES) {
                v0 = *(const float4*)(A0 + (size_t)gm * C + k0 + ak);
                v1 = *(const float4*)(A1 + (size_t)gm * C + k0 + ak);
            }
            sA0[ak + 0][row] = v0.x; sA0[ak + 1][row] = v0.y;
            sA0[ak + 2][row] = v0.z; sA0[ak + 3][row] = v0.w;
            sA1[ak + 0][row] = v1.x; sA1[ak + 1][row] = v1.y;
            sA1[ak + 2][row] = v1.z; sA1[ak + 3][row] = v1.w;
        }
        // load W tiles
        #pragma unroll
        for (int r = 0; r < WIT; r++) {
            int id = tid + r * 256;
            int kk = id / (BN / 4);
            int nn = (id % (BN / 4)) * 4;
            *(float4*)&sW0[kk][nn] = *(const float4*)(W0 + (size_t)(k0 + kk) * BN + nn);
            *(float4*)&sW1[kk][nn] = *(const float4*)(W1 + (size_t)(k0 + kk) * BN + nn);
        }
        __syncthreads();

        #pragma unroll
        for (int k = 0; k < BK; k++) {
            float a0[TM], a1[TM], w0[TN], w1[TN];
            #pragma unroll
            for (int i = 0; i < TM; i += 4) {
                float4 t = *(const float4*)&sA0[k][ty * TM + i];
                a0[i] = t.x; a0[i + 1] = t.y; a0[i + 2] = t.z; a0[i + 3] = t.w;
                float4 u = *(const float4*)&sA1[k][ty * TM + i];
                a1[i] = u.x; a1[i + 1] = u.y; a1[i + 2] = u.z; a1[i + 3] = u.w;
            }
            #pragma unroll
            for (int j = 0; j < TN; j += 4) {
                float4 t = *(const float4*)&sW0[k][tx * TN + j];
                w0[j] = t.x; w0[j + 1] = t.y; w0[j + 2] = t.z; w0[j + 3] = t.w;
                float4 u = *(const float4*)&sW1[k][tx * TN + j];
                w1[j] = u.x; w1[j + 1] = u.y; w1[j + 2] = u.z; w1[j + 3] = u.w;
            }
            #pragma unroll
            for (int i = 0; i < TM; i++)
                #pragma unroll
                for (int j = 0; j < TN; j++)
                    acc[i][j] = fmaf(a1[i], w1[j], fmaf(a0[i], w0[j], acc[i][j]));
        }
        __syncthreads();
    }

    #pragma unroll
    for (int i = 0; i < TM; i++) {
        int m = m0 + ty * TM + i;
        if (m < N_NODES) {
            #pragma unroll
            for (int j = 0; j < TN; j += 4) {
                int n = tx * TN + j;
                float4 v;
                v.x = acc[i][j]; v.y = acc[i][j + 1];
                v.z = acc[i][j + 2]; v.w = acc[i][j + 3];
                if (bias) {
                    v.x += bias[n]; v.y += bias[n + 1];
                    v.z += bias[n + 2]; v.w += bias[n + 3];
                }
                *(float4*)(H + (size_t)m * BN + n) = v;
            }
        }
    }
}

// ---------------- BatchNorm pieces ----------------
__global__ void zero_stats_kernel() {
    int i = threadIdx.x;
    if (i < C) { g_sum[i] = 0.f; g_sumsq[i] = 0.f; }
}

__global__ void colstats_kernel(const float* __restrict__ h) {
    int c = threadIdx.x;            // 128 threads
    int r0 = blockIdx.x * 64;
    int r1 = min(r0 + 64, N_NODES);
    float s = 0.f, q = 0.f;
    for (int r = r0; r < r1; r++) {
        float v = h[(size_t)r * C + c];
        s += v;
        q += v * v;
    }
    atomicAdd(&g_sum[c], s);
    atomicAdd(&g_sumsq[c], q);
}

__global__ void bn_finalize_kernel(const float* __restrict__ gamma,
                                   const float* __restrict__ beta) {
    int c = threadIdx.x;  // 128
    float mean = g_sum[c] * (1.f / N_NODES);
    float var = g_sumsq[c] * (1.f / N_NODES) - mean * mean;
    float sc = gamma[c] * rsqrtf(var + BN_EPS);
    g_scale[c] = sc;
    g_shift[c] = beta[c] - mean * sc;
}

// x_out = relu(h * scale + shift + x_in)
__global__ void bn_apply_kernel(const float* __restrict__ h,
                                const float* __restrict__ xin,
                                float* __restrict__ xout) {
    int i = blockIdx.x * blockDim.x + threadIdx.x;  // float4 index
    if (i >= N_NODES * (C / 4)) return;
    int c = (i & 31) << 2;
    float4 hv = ((const float4*)h)[i];
    float4 xv = ((const float4*)xin)[i];
    float4 sc = *(const float4*)(g_scale + c);
    float4 sh = *(const float4*)(g_shift + c);
    float4 o;
    o.x = fmaxf(fmaf(hv.x, sc.x, sh.x) + xv.x, 0.f);
    o.y = fmaxf(fmaf(hv.y, sc.y, sh.y) + xv.y, 0.f);
    o.z = fmaxf(fmaf(hv.z, sc.z, sh.z) + xv.z, 0.f);
    o.w = fmaxf(fmaf(hv.w, sc.w, sh.w) + xv.w, 0.f);
    ((float4*)xout)[i] = o;
}

// ---------------- launch ----------------
extern "C" void kernel_launch(void* const* d_in, const int* in_sizes, int n_in,
                              void* d_out, int out_size) {
    const float* x    = (const float*)d_in[0];
    const int*   esrc = (const int*)d_in[1];
    const int*   edst = (const int*)d_in[2];
    const float* ew   = (const float*)d_in[3];
    const float* Wr0  = (const float*)d_in[4];
    // d_in[5] = b_rel0: cancels exactly under BN (mean subtracts it) -> skipped
    const float* Wo0  = (const float*)d_in[6];
    const float* Wr1  = (const float*)d_in[7];
    // d_in[8] = b_rel1: cancels under BN -> skipped
    const float* Wo1  = (const float*)d_in[9];
    const float* Wr2  = (const float*)d_in[10];
    const float* b2   = (const float*)d_in[11];
    const float* Wo2  = (const float*)d_in[12];
    const float* gamma0 = (const float*)d_in[13];
    const float* beta0  = (const float*)d_in[14];
    const float* gamma1 = (const float*)d_in[15];
    const float* beta1  = (const float*)d_in[16];
    float* out = (float*)d_out;

    float *agg, *h, *x1, *x2;
    cudaGetSymbolAddress((void**)&agg, g_agg);
    cudaGetSymbolAddress((void**)&h,   g_h);
    cudaGetSymbolAddress((void**)&x1,  g_x1);
    cudaGetSymbolAddress((void**)&x2,  g_x2);

    const int EB = (N_EDGES + 255) / 256;          // 3125
    const int AGG_B = (N_NODES + 7) / 8;           // 6250 (8 warps/block)
    const int GEMM_B = (N_NODES + 127) / 128;      // 391
    const int STAT_B = (N_NODES + 63) / 64;        // 782
    const int APPLY_B = (N_NODES * (C / 4) + 255) / 256;  // 6250

    // CSR build (once per launch; reused by all 3 layers)
    zero_deg_kernel<<<(N_NODES + 256) / 256, 256>>>();
    hist_kernel<<<EB, 256>>>(edst);
    scan_kernel<<<1, 1024>>>();
    build_csr_kernel<<<EB, 256>>>(esrc, edst, ew);

    // ---- layer 0 ----
    aggregate_kernel<<<AGG_B, 256>>>(x, agg);
    gemm_dual_kernel<128><<<GEMM_B, 256>>>(agg, x, Wr0, Wo0, nullptr, h);
    zero_stats_kernel<<<1, 128>>>();
    colstats_kernel<<<STAT_B, 128>>>(h);
    bn_finalize_kernel<<<1, 128>>>(gamma0, beta0);
    bn_apply_kernel<<<APPLY_B, 256>>>(h, x, x1);

    // ---- layer 1 ----
    aggregate_kernel<<<AGG_B, 256>>>(x1, agg);
    gemm_dual_kernel<128><<<GEMM_B, 256>>>(agg, x1, Wr1, Wo1, nullptr, h);
    zero_stats_kernel<<<1, 128>>>();
    colstats_kernel<<<STAT_B, 128>>>(h);
    bn_finalize_kernel<<<1, 128>>>(gamma1, beta1);
    bn_apply_kernel<<<APPLY_B, 256>>>(h, x1, x2);

    // ---- layer 2 (no BN/residual/relu, has bias, OUT=64) ----
    aggregate_kernel<<<AGG_B, 256>>>(x2, agg);
    gemm_dual_kernel<64><<<GEMM_B, 256>>>(agg, x2, Wr2, Wo2, b2, out);
}

// round 2
// speedup vs baseline: 1.0433x; 1.0433x over previous
#include <cuda_runtime.h>

#define N_NODES 50000
#define N_EDGES 800000
#define C 128
#define OUTC 64
#define BN_EPS 1e-5f

typedef unsigned long long u64;

__device__ __forceinline__ u64 pack2(float lo, float hi) {
    u64 r; asm("mov.b64 %0,{%1,%2};" : "=l"(r) : "f"(lo), "f"(hi)); return r;
}
__device__ __forceinline__ float2 unpack2(u64 v) {
    float2 r; asm("mov.b64 {%0,%1},%2;" : "=f"(r.x), "=f"(r.y) : "l"(v)); return r;
}
__device__ __forceinline__ void ffma2(u64& d, u64 a, u64 b) {
    asm("fma.rn.f32x2 %0,%1,%2,%0;" : "+l"(d) : "l"(a), "l"(b));
}

// ---------------- scratch (no allocations allowed) ----------------
__device__ int   g_off[N_NODES + 1];
__device__ int   g_cursor[N_NODES];
__device__ int   g_srcs[N_EDGES];
__device__ float g_ws[N_EDGES];
__device__ float g_agg[N_NODES * C];
__device__ float g_h[N_NODES * C];
__device__ float g_x1[N_NODES * C];
__device__ float g_x2[N_NODES * C];
__device__ float g_sum[2 * C];
__device__ float g_sumsq[2 * C];
__device__ float g_scale[C];
__device__ float g_shift[C];

// ---------------- init: zero degree counts + BN stat accumulators ----------------
__global__ void init_kernel() {
    int i = blockIdx.x * blockDim.x + threadIdx.x;
    if (i <= N_NODES) g_off[i] = 0;
    if (i < 2 * C) { g_sum[i] = 0.f; g_sumsq[i] = 0.f; }
}

__global__ void hist_kernel(const int* __restrict__ dst) {
    int e = blockIdx.x * blockDim.x + threadIdx.x;
    if (e < N_EDGES) atomicAdd(&g_off[dst[e]], 1);
}

// single-block scan: counts (in g_off) -> exclusive offsets (in-place) + cursor copy
__global__ void scan_kernel() {
    __shared__ int warp_sums[32];
    __shared__ int carry;
    const int tid = threadIdx.x;
    const int lane = tid & 31;
    const int wid = tid >> 5;
    if (tid == 0) carry = 0;
    __syncthreads();
    for (int base = 0; base < N_NODES; base += 1024) {
        int i = base + tid;
        int v = (i < N_NODES) ? g_off[i] : 0;
        int x = v;
        #pragma unroll
        for (int s = 1; s < 32; s <<= 1) {
            int t = __shfl_up_sync(0xFFFFFFFFu, x, s);
            if (lane >= s) x += t;
        }
        if (lane == 31) warp_sums[wid] = x;
        __syncthreads();
        if (wid == 0) {
            int ws = warp_sums[lane];
            #pragma unroll
            for (int s = 1; s < 32; s <<= 1) {
                int t = __shfl_up_sync(0xFFFFFFFFu, ws, s);
                if (lane >= s) ws += t;
            }
            warp_sums[lane] = ws;
        }
        __syncthreads();
        int warp_prefix = (wid > 0) ? warp_sums[wid - 1] : 0;
        int excl = x + warp_prefix + carry - v;
        if (i < N_NODES) { g_off[i] = excl; g_cursor[i] = excl; }
        __syncthreads();
        if (tid == 0) carry += warp_sums[31];
        __syncthreads();
    }
    if (tid == 0) g_off[N_NODES] = carry;
}

__global__ void build_csr_kernel(const int* __restrict__ src,
                                 const int* __restrict__ dst,
                                 const float* __restrict__ w) {
    int e = blockIdx.x * blockDim.x + threadIdx.x;
    if (e < N_EDGES) {
        int d = dst[e];
        int p = atomicAdd(&g_cursor[d], 1);
        g_srcs[p] = src[e];
        g_ws[p] = w[e];
    }
}

// ---------------- aggregation: one warp per destination node ----------------
__global__ void aggregate_kernel(const float* __restrict__ x, float* __restrict__ agg) {
    int gw = (blockIdx.x * blockDim.x + threadIdx.x) >> 5;
    int lane = threadIdx.x & 31;
    if (gw >= N_NODES) return;
    int j = g_off[gw];
    int e = g_off[gw + 1];
    float4 acc = make_float4(0.f, 0.f, 0.f, 0.f);
    // unrolled by 2 for MLP against L2 latency
    for (; j + 1 < e; j += 2) {
        int s0 = g_srcs[j];
        int s1 = g_srcs[j + 1];
        float w0 = g_ws[j];
        float w1 = g_ws[j + 1];
        float4 v0 = __ldg((const float4*)(x + (size_t)s0 * C) + lane);
        float4 v1 = __ldg((const float4*)(x + (size_t)s1 * C) + lane);
        acc.x = fmaf(w0, v0.x, acc.x); acc.y = fmaf(w0, v0.y, acc.y);
        acc.z = fmaf(w0, v0.z, acc.z); acc.w = fmaf(w0, v0.w, acc.w);
        acc.x = fmaf(w1, v1.x, acc.x); acc.y = fmaf(w1, v1.y, acc.y);
        acc.z = fmaf(w1, v1.z, acc.z); acc.w = fmaf(w1, v1.w, acc.w);
    }
    if (j < e) {
        int s = g_srcs[j];
        float w = g_ws[j];
        float4 v = __ldg((const float4*)(x + (size_t)s * C) + lane);
        acc.x = fmaf(w, v.x, acc.x); acc.y = fmaf(w, v.y, acc.y);
        acc.z = fmaf(w, v.z, acc.z); acc.w = fmaf(w, v.w, acc.w);
    }
    ((float4*)(agg + (size_t)gw * C))[lane] = acc;
}

// ---------------- fused dual GEMM (packed f32x2): H = A0@W0 + A1@W1 (+bias) ----------------
// Optionally computes per-column sum/sumsq (BN stats) fused in the epilogue.
template <int BN, bool STATS>
__global__ void __launch_bounds__(256, 2) gemm_dual_kernel(
    const float* __restrict__ A0, const float* __restrict__ A1,
    const float* __restrict__ W0, const float* __restrict__ W1,
    const float* __restrict__ bias, float* __restrict__ H, int layer) {
    constexpr int BM = 128, BK = 16, TM = 8;
    constexpr int TN = BN / 16;
    __shared__ __align__(16) float sA0[BK][BM];
    __shared__ __align__(16) float sA1[BK][BM];
    __shared__ __align__(16) float sW0[BK][BN];
    __shared__ __align__(16) float sW1[BK][BN];
    __shared__ float ssum[BN];
    __shared__ float ssq[BN];

    const int tid = threadIdx.x;
    const int tx = tid & 15;   // col group
    const int ty = tid >> 4;   // row group
    const int m0 = blockIdx.x * BM;

    u64 acc2[TM][TN / 2];
    #pragma unroll
    for (int i = 0; i < TM; i++)
        #pragma unroll
        for (int j = 0; j < TN / 2; j++) acc2[i][j] = pack2(0.f, 0.f);

    const int ar = tid >> 2;          // 0..63
    const int ak = (tid & 3) << 2;    // 0,4,8,12
    constexpr int WIT = (BK * BN / 4) / 256;  // 2 for BN=128, 1 for BN=64

    for (int k0 = 0; k0 < C; k0 += BK) {
        #pragma unroll
        for (int r = 0; r < 2; r++) {
            int row = ar + r * 64;
            int gm = m0 + row;
            float4 v0 = make_float4(0.f, 0.f, 0.f, 0.f);
            float4 v1 = make_float4(0.f, 0.f, 0.f, 0.f);
            if (gm < N_NODES) {
                v0 = *(const float4*)(A0 + (size_t)gm * C + k0 + ak);
                v1 = *(const float4*)(A1 + (size_t)gm * C + k0 + ak);
            }
            sA0[ak + 0][row] = v0.x; sA0[ak + 1][row] = v0.y;
            sA0[ak + 2][row] = v0.z; sA0[ak + 3][row] = v0.w;
            sA1[ak + 0][row] = v1.x; sA1[ak + 1][row] = v1.y;
            sA1[ak + 2][row] = v1.z; sA1[ak + 3][row] = v1.w;
        }
        #pragma unroll
        for (int r = 0; r < WIT; r++) {
            int id = tid + r * 256;
            int kk = id / (BN / 4);
            int nn = (id % (BN / 4)) * 4;
            *(float4*)&sW0[kk][nn] = *(const float4*)(W0 + (size_t)(k0 + kk) * BN + nn);
            *(float4*)&sW1[kk][nn] = *(const float4*)(W1 + (size_t)(k0 + kk) * BN + nn);
        }
        __syncthreads();

        #pragma unroll
        for (int k = 0; k < BK; k++) {
            u64 w0p[TN / 2], w1p[TN / 2];
            #pragma unroll
            for (int j = 0; j < TN / 2; j++) {
                w0p[j] = *(const u64*)&sW0[k][tx * TN + 2 * j];
                w1p[j] = *(const u64*)&sW1[k][tx * TN + 2 * j];
            }
            #pragma unroll
            for (int i = 0; i < TM; i += 4) {
                float4 t = *(const float4*)&sA0[k][ty * TM + i];
                float4 u = *(const float4*)&sA1[k][ty * TM + i];
                u64 a0p0 = pack2(t.x, t.x), a0p1 = pack2(t.y, t.y);
                u64 a0p2 = pack2(t.z, t.z), a0p3 = pack2(t.w, t.w);
                u64 a1p0 = pack2(u.x, u.x), a1p1 = pack2(u.y, u.y);
                u64 a1p2 = pack2(u.z, u.z), a1p3 = pack2(u.w, u.w);
                #pragma unroll
                for (int j = 0; j < TN / 2; j++) {
                    ffma2(acc2[i + 0][j], a0p0, w0p[j]); ffma2(acc2[i + 0][j], a1p0, w1p[j]);
                    ffma2(acc2[i + 1][j], a0p1, w0p[j]); ffma2(acc2[i + 1][j], a1p1, w1p[j]);
                    ffma2(acc2[i + 2][j], a0p2, w0p[j]); ffma2(acc2[i + 2][j], a1p2, w1p[j]);
                    ffma2(acc2[i + 3][j], a0p3, w0p[j]); ffma2(acc2[i + 3][j], a1p3, w1p[j]);
                }
            }
        }
        __syncthreads();
    }

    if (STATS) {
        if (tid < BN) { ssum[tid] = 0.f; ssq[tid] = 0.f; }
        __syncthreads();
    }

    #pragma unroll
    for (int i = 0; i < TM; i++) {
        int m = m0 + ty * TM + i;
        float v[TN];
        #pragma unroll
        for (int j = 0; j < TN / 2; j++) {
            float2 p = unpack2(acc2[i][j]);
            v[2 * j] = p.x; v[2 * j + 1] = p.y;
        }
        if (m < N_NODES) {
            #pragma unroll
            for (int j = 0; j < TN; j += 4) {
                int n = tx * TN + j;
                float4 o = make_float4(v[j], v[j + 1], v[j + 2], v[j + 3]);
                if (bias) {
                    o.x += bias[n]; o.y += bias[n + 1];
                    o.z += bias[n + 2]; o.w += bias[n + 3];
                }
                *(float4*)(H + (size_t)m * BN + n) = o;
            }
        }
    }

    if (STATS) {
        // OOB rows carry acc=0 (zero-filled loads) -> contribute nothing
        #pragma unroll
        for (int j = 0; j < TN / 2; j++) {
            float sx = 0.f, sy = 0.f, qx = 0.f, qy = 0.f;
            #pragma unroll
            for (int i = 0; i < TM; i++) {
                float2 p = unpack2(acc2[i][j]);
                sx += p.x; qx += p.x * p.x;
                sy += p.y; qy += p.y * p.y;
            }
            int n = tx * TN + 2 * j;
            atomicAdd(&ssum[n], sx); atomicAdd(&ssum[n + 1], sy);
            atomicAdd(&ssq[n], qx);  atomicAdd(&ssq[n + 1], qy);
        }
        __syncthreads();
        if (tid < BN) {
            atomicAdd(&g_sum[layer * C + tid], ssum[tid]);
            atomicAdd(&g_sumsq[layer * C + tid], ssq[tid]);
        }
    }
}

// ---------------- BatchNorm finalize + apply ----------------
__global__ void bn_finalize_kernel(const float* __restrict__ gamma,
                                   const float* __restrict__ beta, int layer) {
    int c = threadIdx.x;  // 128
    float mean = g_sum[layer * C + c] * (1.f / N_NODES);
    float var = g_sumsq[layer * C + c] * (1.f / N_NODES) - mean * mean;
    float sc = gamma[c] * rsqrtf(var + BN_EPS);
    g_scale[c] = sc;
    g_shift[c] = beta[c] - mean * sc;
}

// x_out = relu(h * scale + shift + x_in)
__global__ void bn_apply_kernel(const float* __restrict__ h,
                                const float* __restrict__ xin,
                                float* __restrict__ xout) {
    int i = blockIdx.x * blockDim.x + threadIdx.x;  // float4 index
    if (i >= N_NODES * (C / 4)) return;
    int c = (i & 31) << 2;
    float4 hv = ((const float4*)h)[i];
    float4 xv = ((const float4*)xin)[i];
    float4 sc = *(const float4*)(g_scale + c);
    float4 sh = *(const float4*)(g_shift + c);
    float4 o;
    o.x = fmaxf(fmaf(hv.x, sc.x, sh.x) + xv.x, 0.f);
    o.y = fmaxf(fmaf(hv.y, sc.y, sh.y) + xv.y, 0.f);
    o.z = fmaxf(fmaf(hv.z, sc.z, sh.z) + xv.z, 0.f);
    o.w = fmaxf(fmaf(hv.w, sc.w, sh.w) + xv.w, 0.f);
    ((float4*)xout)[i] = o;
}

// ---------------- launch ----------------
extern "C" void kernel_launch(void* const* d_in, const int* in_sizes, int n_in,
                              void* d_out, int out_size) {
    const float* x    = (const float*)d_in[0];
    const int*   esrc = (const int*)d_in[1];
    const int*   edst = (const int*)d_in[2];
    const float* ew   = (const float*)d_in[3];
    const float* Wr0  = (const float*)d_in[4];
    // d_in[5] = b_rel0: cancels exactly under BN -> skipped
    const float* Wo0  = (const float*)d_in[6];
    const float* Wr1  = (const float*)d_in[7];
    // d_in[8] = b_rel1: cancels under BN -> skipped
    const float* Wo1  = (const float*)d_in[9];
    const float* Wr2  = (const float*)d_in[10];
    const float* b2   = (const float*)d_in[11];
    const float* Wo2  = (const float*)d_in[12];
    const float* gamma0 = (const float*)d_in[13];
    const float* beta0  = (const float*)d_in[14];
    const float* gamma1 = (const float*)d_in[15];
    const float* beta1  = (const float*)d_in[16];
    float* out = (float*)d_out;

    float *agg, *h, *x1, *x2;
    cudaGetSymbolAddress((void**)&agg, g_agg);
    cudaGetSymbolAddress((void**)&h,   g_h);
    cudaGetSymbolAddress((void**)&x1,  g_x1);
    cudaGetSymbolAddress((void**)&x2,  g_x2);

    const int EB = (N_EDGES + 255) / 256;
    const int AGG_B = (N_NODES + 7) / 8;
    const int GEMM_B = (N_NODES + 127) / 128;
    const int APPLY_B = (N_NODES * (C / 4) + 255) / 256;

    // CSR build + stat zeroing (once per launch; reused by all 3 layers)
    init_kernel<<<(N_NODES + 256) / 256, 256>>>();
    hist_kernel<<<EB, 256>>>(edst);
    scan_kernel<<<1, 1024>>>();
    build_csr_kernel<<<EB, 256>>>(esrc, edst, ew);

    // ---- layer 0 ----
    aggregate_kernel<<<AGG_B, 256>>>(x, agg);
    gemm_dual_kernel<128, true><<<GEMM_B, 256>>>(agg, x, Wr0, Wo0, nullptr, h, 0);
    bn_finalize_kernel<<<1, 128>>>(gamma0, beta0, 0);
    bn_apply_kernel<<<APPLY_B, 256>>>(h, x, x1);

    // ---- layer 1 ----
    aggregate_kernel<<<AGG_B, 256>>>(x1, agg);
    gemm_dual_kernel<128, true><<<GEMM_B, 256>>>(agg, x1, Wr1, Wo1, nullptr, h, 1);
    bn_finalize_kernel<<<1, 128>>>(gamma1, beta1, 1);
    bn_apply_kernel<<<APPLY_B, 256>>>(h, x1, x2);

    // ---- layer 2 (no BN/residual/relu, has bias, OUT=64) ----
    aggregate_kernel<<<AGG_B, 256>>>(x2, agg);
    gemm_dual_kernel<64, false><<<GEMM_B, 256>>>(agg, x2, Wr2, Wo2, b2, out, 0);
}

// round 4
// speedup vs baseline: 1.2191x; 1.1685x over previous
#include <cuda_runtime.h>
#include <cuda_bf16.h>
#include <cstdint>

#define N_NODES 50000
#define N_EDGES 800000
#define C 128
#define BN_EPS 1e-5f

// ================= PTX helpers (sm_100-safe: mma.sync / ldmatrix / cp.async) =================
__device__ __forceinline__ uint32_t smem_u32(const void* p) {
    uint32_t a;
    asm("{ .reg .u64 t; cvta.to.shared.u64 t, %1; cvt.u32.u64 %0, t; }" : "=r"(a) : "l"(p));
    return a;
}
__device__ __forceinline__ void cpa16(uint32_t dst, const void* src, uint32_t sz) {
    asm volatile("cp.async.cg.shared.global [%0], [%1], 16, %2;" :: "r"(dst), "l"(src), "r"(sz));
}
#define CP_COMMIT() asm volatile("cp.async.commit_group;" ::: "memory")
__device__ __forceinline__ void ldsm_x4(uint32_t* r, uint32_t a) {
    asm volatile("ldmatrix.sync.aligned.m8n8.x4.shared.b16 {%0,%1,%2,%3}, [%4];"
                 : "=r"(r[0]), "=r"(r[1]), "=r"(r[2]), "=r"(r[3]) : "r"(a));
}
__device__ __forceinline__ void ldsm_x2(uint32_t* r, uint32_t a) {
    asm volatile("ldmatrix.sync.aligned.m8n8.x2.shared.b16 {%0,%1}, [%2];"
                 : "=r"(r[0]), "=r"(r[1]) : "r"(a));
}
__device__ __forceinline__ void mma16816(float* d, const uint32_t* a, const uint32_t* b) {
    asm volatile(
        "mma.sync.aligned.m16n8k16.row.col.f32.bf16.bf16.f32 "
        "{%0,%1,%2,%3},{%4,%5,%6,%7},{%8,%9},{%0,%1,%2,%3};"
        : "+f"(d[0]), "+f"(d[1]), "+f"(d[2]), "+f"(d[3])
        : "r"(a[0]), "r"(a[1]), "r"(a[2]), "r"(a[3]), "r"(b[0]), "r"(b[1]));
}

// ================= scratch =================
__device__ int   g_off[N_NODES + 1];
__device__ int   g_cursor[N_NODES];
__device__ int   g_srcs[N_EDGES];
__device__ float g_ws[N_EDGES];
__device__ float g_h[N_NODES * C];
__device__ float g_x1[N_NODES * C];
__device__ float g_x2[N_NODES * C];
__device__ __nv_bfloat16 g_aggh[N_NODES * C];
__device__ __nv_bfloat16 g_aggl[N_NODES * C];
__device__ __nv_bfloat16 g_xh[N_NODES * C];
__device__ __nv_bfloat16 g_xl[N_NODES * C];
__device__ __nv_bfloat16 g_bt0[12 * 128 * 64];
__device__ __nv_bfloat16 g_bt1[12 * 128 * 64];
__device__ __nv_bfloat16 g_bt2[12 * 64 * 64];
__device__ float g_sum[2 * C];
__device__ float g_sumsq[2 * C];
__device__ float g_scale[C];
__device__ float g_shift[C];

// ================= bf16 hi/lo split helper =================
__device__ __forceinline__ void split_store4(float4 v, __nv_bfloat16* ph, __nv_bfloat16* pl) {
    __nv_bfloat16 hx = __float2bfloat16_rn(v.x), hy = __float2bfloat16_rn(v.y),
                  hz = __float2bfloat16_rn(v.z), hw = __float2bfloat16_rn(v.w);
    __nv_bfloat16 lx = __float2bfloat16_rn(v.x - __bfloat162float(hx)),
                  ly = __float2bfloat16_rn(v.y - __bfloat162float(hy)),
                  lz = __float2bfloat16_rn(v.z - __bfloat162float(hz)),
                  lw = __float2bfloat16_rn(v.w - __bfloat162float(hw));
    __nv_bfloat162 h0 = __halves2bfloat162(hx, hy), h1 = __halves2bfloat162(hz, hw);
    __nv_bfloat162 l0 = __halves2bfloat162(lx, ly), l1 = __halves2bfloat162(lz, lw);
    *(uint2*)ph = make_uint2(*(uint32_t*)&h0, *(uint32_t*)&h1);
    *(uint2*)pl = make_uint2(*(uint32_t*)&l0, *(uint32_t*)&l1);
}

// ================= CSR build =================
__global__ void init_kernel() {
    int i = blockIdx.x * blockDim.x + threadIdx.x;
    if (i <= N_NODES) g_off[i] = 0;
    if (i < 2 * C) { g_sum[i] = 0.f; g_sumsq[i] = 0.f; }
}

__global__ void hist_kernel(const int* __restrict__ dst) {
    int e = blockIdx.x * blockDim.x + threadIdx.x;
    if (e < N_EDGES) atomicAdd(&g_off[dst[e]], 1);
}

__global__ void scan_kernel() {
    __shared__ int warp_sums[32];
    __shared__ int carry;
    const int tid = threadIdx.x;
    const int lane = tid & 31;
    const int wid = tid >> 5;
    if (tid == 0) carry = 0;
    __syncthreads();
    for (int base = 0; base < N_NODES; base += 1024) {
        int i = base + tid;
        int v = (i < N_NODES) ? g_off[i] : 0;
        int x = v;
        #pragma unroll
        for (int s = 1; s < 32; s <<= 1) {
            int t = __shfl_up_sync(0xFFFFFFFFu, x, s);
            if (lane >= s) x += t;
        }
        if (lane == 31) warp_sums[wid] = x;
        __syncthreads();
        if (wid == 0) {
            int ws = warp_sums[lane];
            #pragma unroll
            for (int s = 1; s < 32; s <<= 1) {
                int t = __shfl_up_sync(0xFFFFFFFFu, ws, s);
                if (lane >= s) ws += t;
            }
            warp_sums[lane] = ws;
        }
        __syncthreads();
        int warp_prefix = (wid > 0) ? warp_sums[wid - 1] : 0;
        int excl = x + warp_prefix + carry - v;
        if (i < N_NODES) { g_off[i] = excl; g_cursor[i] = excl; }
        __syncthreads();
        if (tid == 0) carry += warp_sums[31];
        __syncthreads();
    }
    if (tid == 0) g_off[N_NODES] = carry;
}

__global__ void build_csr_kernel(const int* __restrict__ src,
                                 const int* __restrict__ dst,
                                 const float* __restrict__ w) {
    int e = blockIdx.x * blockDim.x + threadIdx.x;
    if (e < N_EDGES) {
        int d = dst[e];
        int p = atomicAdd(&g_cursor[d], 1);
        g_srcs[p] = src[e];
        g_ws[p] = w[e];
    }
}

// ================= B-tile setup: W -> [n][k] bf16 hi/lo slices =================
// 12 slices s = q*2 + khalf; q in 0..5: (path = q/3: 0 rel, 1 root; lo = (q%3==1))
// Slice layout: [NN rows(n)][64 cols(k)] bf16, dense (128B rows).
template <int NN>
__global__ void build_bt_kernel(const float* __restrict__ Wrel,
                                const float* __restrict__ Wroot,
                                __nv_bfloat16* __restrict__ Bt) {
    int idx = blockIdx.x * 256 + threadIdx.x;
    if (idx >= 12 * NN * 64) return;
    int s = idx / (NN * 64);
    int r = idx % (NN * 64);
    int n = r / 64;
    int kk = r % 64;
    int q = s >> 1;
    int kh = s & 1;
    const float* W = (q < 3) ? Wrel : Wroot;
    bool lo = ((q % 3) == 1);
    float w = W[(size_t)(kh * 64 + kk) * NN + n];
    __nv_bfloat16 hv = __float2bfloat16_rn(w);
    __nv_bfloat16 val = lo ? __float2bfloat16_rn(w - __bfloat162float(hv)) : hv;
    Bt[(size_t)s * NN * 64 + n * 64 + kk] = val;
}

// ================= initial x -> hi/lo split =================
__global__ void split_x_kernel(const float* __restrict__ x) {
    int i = blockIdx.x * blockDim.x + threadIdx.x;
    if (i >= N_NODES * (C / 4)) return;
    float4 v = ((const float4*)x)[i];
    split_store4(v, g_xh + (size_t)i * 4, g_xl + (size_t)i * 4);
}

// ================= aggregation: one warp per destination, writes bf16 hi/lo =================
__global__ void aggregate_kernel(const float* __restrict__ x) {
    int gw = (blockIdx.x * blockDim.x + threadIdx.x) >> 5;
    int lane = threadIdx.x & 31;
    if (gw >= N_NODES) return;
    int j = g_off[gw];
    int e = g_off[gw + 1];
    float4 acc = make_float4(0.f, 0.f, 0.f, 0.f);
    for (; j + 1 < e; j += 2) {
        int s0 = g_srcs[j];
        int s1 = g_srcs[j + 1];
        float w0 = g_ws[j];
        float w1 = g_ws[j + 1];
        float4 v0 = __ldg((const float4*)(x + (size_t)s0 * C) + lane);
        float4 v1 = __ldg((const float4*)(x + (size_t)s1 * C) + lane);
        acc.x = fmaf(w0, v0.x, acc.x); acc.y = fmaf(w0, v0.y, acc.y);
        acc.z = fmaf(w0, v0.z, acc.z); acc.w = fmaf(w0, v0.w, acc.w);
        acc.x = fmaf(w1, v1.x, acc.x); acc.y = fmaf(w1, v1.y, acc.y);
        acc.z = fmaf(w1, v1.z, acc.z); acc.w = fmaf(w1, v1.w, acc.w);
    }
    if (j < e) {
        int s = g_srcs[j];
        float w = g_ws[j];
        float4 v = __ldg((const float4*)(x + (size_t)s * C) + lane);
        acc.x = fmaf(w, v.x, acc.x); acc.y = fmaf(w, v.y, acc.y);
        acc.z = fmaf(w, v.z, acc.z); acc.w = fmaf(w, v.w, acc.w);
    }
    size_t base = (size_t)gw * C + lane * 4;
    split_store4(acc, g_aggh + base, g_aggl + base);
}

// ================= HMMA GEMM: H[128,NN] = agg@Wrel + x@Wroot (bf16x3 split) =================
// 12 iters (= slices) of K=64; A sources per q: [Ah, Ah, Al, Xh, Xh, Xl].
// SMEM rows padded to 144B: conflict-light ldmatrix, 16B-aligned.
template <int NN, bool STATS>
__global__ void __launch_bounds__(256) mma_gemm_kernel(
    const __nv_bfloat16* __restrict__ Ah, const __nv_bfloat16* __restrict__ Al,
    const __nv_bfloat16* __restrict__ Xh, const __nv_bfloat16* __restrict__ Xl,
    const __nv_bfloat16* __restrict__ Bt,
    const float* __restrict__ bias, float* __restrict__ H, int layer) {
    constexpr int WM = (NN == 128) ? 2 : 4;     // warps along M
    constexpr int WN = 8 / WM;                  // warps along N
    constexpr int MF = 128 / (WM * 16);         // m16 frags per warp
    constexpr int NF = NN / (WN * 8);           // n8 frags per warp
    constexpr int PITCH = 144;
    constexpr int ABYTES = 128 * PITCH;
    constexpr int BBYTES = NN * PITCH;

    extern __shared__ __align__(16) char smem[];
    const uint32_t sb = smem_u32(smem);
    const uint32_t sA[2] = {sb, sb + ABYTES};
    const uint32_t sB[2] = {sb + 2 * ABYTES, sb + 2 * ABYTES + BBYTES};
    __shared__ float ssum[NN], ssq[NN];

    const int tid = threadIdx.x;
    const int wid = tid >> 5;
    const int lane = tid & 31;
    const int m0 = blockIdx.x * 128;
    const int wmb = (wid / WN) * (MF * 16);
    const int wnb = (wid % WN) * (NF * 8);

    const __nv_bfloat16* asrc[6] = {Ah, Ah, Al, Xh, Xh, Xl};

    float acc[MF][NF][4];
    #pragma unroll
    for (int i = 0; i < MF; i++)
        #pragma unroll
        for (int j = 0; j < NF; j++)
            #pragma unroll
            for (int k = 0; k < 4; k++) acc[i][j][k] = 0.f;

    auto load_tile = [&](int it) {
        int q = it >> 1, kh = it & 1, buf = it & 1;
        const __nv_bfloat16* As = asrc[q];
        #pragma unroll
        for (int u = 0; u < 4; u++) {
            int unit = tid + u * 256;
            int row = unit >> 3, cu = unit & 7;
            int m = m0 + row;
            cpa16(sA[buf] + row * PITCH + cu * 16,
                  (const char*)(As + (size_t)m * C + kh * 64) + cu * 16,
                  (m < N_NODES) ? 16u : 0u);
        }
        const char* Bs = (const char*)(Bt + (size_t)it * NN * 64);
        #pragma unroll
        for (int u = 0; u < NN / 32; u++) {
            int unit = tid + u * 256;
            int n = unit >> 3, cu = unit & 7;
            cpa16(sB[buf] + n * PITCH + cu * 16, Bs + n * 128 + cu * 16, 16u);
        }
    };

    const uint32_t a_lane = (lane & 7) * PITCH + ((lane >> 3) & 1) * 8 * PITCH + (lane >> 4) * 16;
    const uint32_t b_lane = (lane & 7) * PITCH + (((lane & 15) >> 3)) * 16;

    load_tile(0);
    CP_COMMIT();
    for (int it = 0; it < 12; it++) {
        if (it < 11) {
            load_tile(it + 1);
            CP_COMMIT();
            asm volatile("cp.async.wait_group 1;" ::: "memory");
        } else {
            asm volatile("cp.async.wait_group 0;" ::: "memory");
        }
        __syncthreads();
        uint32_t abase = sA[it & 1] + wmb * PITCH + a_lane;
        uint32_t bbase = sB[it & 1] + wnb * PITCH + b_lane;
        #pragma unroll
        for (int ks = 0; ks < 4; ks++) {
            uint32_t a[MF][4], b[NF][2];
            #pragma unroll
            for (int mf = 0; mf < MF; mf++) ldsm_x4(a[mf], abase + mf * 16 * PITCH + ks * 32);
            #pragma unroll
            for (int nf = 0; nf < NF; nf++) ldsm_x2(b[nf], bbase + nf * 8 * PITCH + ks * 32);
            #pragma unroll
            for (int mf = 0; mf < MF; mf++)
                #pragma unroll
                for (int nf = 0; nf < NF; nf++) mma16816(acc[mf][nf], a[mf], b[nf]);
        }
        __syncthreads();
    }

    if (STATS) {
        if (tid < NN) { ssum[tid] = 0.f; ssq[tid] = 0.f; }
        __syncthreads();
    }

    // epilogue: write H (+bias)
    #pragma unroll
    for (int mf = 0; mf < MF; mf++) {
        int r = m0 + wmb + mf * 16 + (lane >> 2);
        #pragma unroll
        for (int nf = 0; nf < NF; nf++) {
            int cc = wnb + nf * 8 + (lane & 3) * 2;
            float b0 = bias ? bias[cc] : 0.f;
            float b1 = bias ? bias[cc + 1] : 0.f;
            if (r < N_NODES)
                *(float2*)(H + (size_t)r * NN + cc) =
                    make_float2(acc[mf][nf][0] + b0, acc[mf][nf][1] + b1);
            if (r + 8 < N_NODES)
                *(float2*)(H + (size_t)(r + 8) * NN + cc) =
                    make_float2(acc[mf][nf][2] + b0, acc[mf][nf][3] + b1);
        }
    }

    if (STATS) {
        // OOB rows hold zeros (cp.async zfill) -> contribute nothing
        #pragma unroll
        for (int nf = 0; nf < NF; nf++) {
            #pragma unroll
            for (int j = 0; j < 2; j++) {
                int col = wnb + nf * 8 + (lane & 3) * 2 + j;
                float s = 0.f, q = 0.f;
                #pragma unroll
                for (int mf = 0; mf < MF; mf++) {
                    float v0 = acc[mf][nf][j];
                    float v1 = acc[mf][nf][2 + j];
                    s += v0 + v1;
                    q += v0 * v0 + v1 * v1;
                }
                atomicAdd(&ssum[col], s);
                atomicAdd(&ssq[col], q);
            }
        }
        __syncthreads();
        if (tid < NN) {
            atomicAdd(&g_sum[layer * C + tid], ssum[tid]);
            atomicAdd(&g_sumsq[layer * C + tid], ssq[tid]);
        }
    }
}

// ================= BatchNorm finalize + apply =================
__global__ void bn_finalize_kernel(const float* __restrict__ gamma,
                                   const float* __restrict__ beta, int layer) {
    int c = threadIdx.x;
    float mean = g_sum[layer * C + c] * (1.f / N_NODES);
    float var = g_sumsq[layer * C + c] * (1.f / N_NODES) - mean * mean;
    float sc = gamma[c] * rsqrtf(var + BN_EPS);
    g_scale[c] = sc;
    g_shift[c] = beta[c] - mean * sc;
}

// x_out = relu(h*scale + shift + x_in); also writes bf16 hi/lo of x_out
__global__ void bn_apply_kernel(const float* __restrict__ h,
                                const float* __restrict__ xin,
                                float* __restrict__ xout) {
    int i = blockIdx.x * blockDim.x + threadIdx.x;
    if (i >= N_NODES * (C / 4)) return;
    int c = (i & 31) << 2;
    float4 hv = ((const float4*)h)[i];
    float4 xv = ((const float4*)xin)[i];
    float4 sc = *(const float4*)(g_scale + c);
    float4 sh = *(const float4*)(g_shift + c);
    float4 o;
    o.x = fmaxf(fmaf(hv.x, sc.x, sh.x) + xv.x, 0.f);
    o.y = fmaxf(fmaf(hv.y, sc.y, sh.y) + xv.y, 0.f);
    o.z = fmaxf(fmaf(hv.z, sc.z, sh.z) + xv.z, 0.f);
    o.w = fmaxf(fmaf(hv.w, sc.w, sh.w) + xv.w, 0.f);
    ((float4*)xout)[i] = o;
    split_store4(o, g_xh + (size_t)i * 4, g_xl + (size_t)i * 4);
}

// ================= launch =================
extern "C" void kernel_launch(void* const* d_in, const int* in_sizes, int n_in,
                              void* d_out, int out_size) {
    const float* x    = (const float*)d_in[0];
    const int*   esrc = (const int*)d_in[1];
    const int*   edst = (const int*)d_in[2];
    const float* ew   = (const float*)d_in[3];
    const float* Wr0  = (const float*)d_in[4];
    // b_rel0 (d_in[5]) cancels exactly under BN
    const float* Wo0  = (const float*)d_in[6];
    const float* Wr1  = (const float*)d_in[7];
    // b_rel1 (d_in[8]) cancels under BN
    const float* Wo1  = (const float*)d_in[9];
    const float* Wr2  = (const float*)d_in[10];
    const float* b2   = (const float*)d_in[11];
    const float* Wo2  = (const float*)d_in[12];
    const float* gamma0 = (const float*)d_in[13];
    const float* beta0  = (const float*)d_in[14];
    const float* gamma1 = (const float*)d_in[15];
    const float* beta1  = (const float*)d_in[16];
    float* out = (float*)d_out;

    float *h, *x1, *x2;
    __nv_bfloat16 *aggh, *aggl, *xh, *xl, *bt0, *bt1, *bt2;
    cudaGetSymbolAddress((void**)&h, g_h);
    cudaGetSymbolAddress((void**)&x1, g_x1);
    cudaGetSymbolAddress((void**)&x2, g_x2);
    cudaGetSymbolAddress((void**)&aggh, g_aggh);
    cudaGetSymbolAddress((void**)&aggl, g_aggl);
    cudaGetSymbolAddress((void**)&xh, g_xh);
    cudaGetSymbolAddress((void**)&xl, g_xl);
    cudaGetSymbolAddress((void**)&bt0, g_bt0);
    cudaGetSymbolAddress((void**)&bt1, g_bt1);
    cudaGetSymbolAddress((void**)&bt2, g_bt2);

    // dynamic SMEM: A 2x18432 + B 2x{18432|9216}
    const int SMEM128 = 2 * 128 * 144 + 2 * 128 * 144;  // 73728
    const int SMEM64  = 2 * 128 * 144 + 2 * 64 * 144;   // 55296
    cudaFuncSetAttribute(mma_gemm_kernel<128, true>,
                         cudaFuncAttributeMaxDynamicSharedMemorySize, SMEM128);
    cudaFuncSetAttribute(mma_gemm_kernel<64, false>,
                         cudaFuncAttributeMaxDynamicSharedMemorySize, SMEM64);

    const int EB = (N_EDGES + 255) / 256;
    const int AGG_B = (N_NODES + 7) / 8;
    const int GEMM_B = (N_NODES + 127) / 128;  // 391
    const int APPLY_B = (N_NODES * (C / 4) + 255) / 256;

    // setup
    init_kernel<<<(N_NODES + 256) / 256, 256>>>();
    hist_kernel<<<EB, 256>>>(edst);
    scan_kernel<<<1, 1024>>>();
    build_csr_kernel<<<EB, 256>>>(esrc, edst, ew);
    build_bt_kernel<128><<<(12 * 128 * 64 + 255) / 256, 256>>>(Wr0, Wo0, bt0);
    build_bt_kernel<128><<<(12 * 128 * 64 + 255) / 256, 256>>>(Wr1, Wo1, bt1);
    build_bt_kernel<64><<<(12 * 64 * 64 + 255) / 256, 256>>>(Wr2, Wo2, bt2);
    split_x_kernel<<<APPLY_B, 256>>>(x);

    // ---- layer 0 ----
    aggregate_kernel<<<AGG_B, 256>>>(x);
    mma_gemm_kernel<128, true><<<GEMM_B, 256, SMEM128>>>(aggh, aggl, xh, xl, bt0, nullptr, h, 0);
    bn_finalize_kernel<<<1, 128>>>(gamma0, beta0, 0);
    bn_apply_kernel<<<APPLY_B, 256>>>(h, x, x1);

    // ---- layer 1 ----
    aggregate_kernel<<<AGG_B, 256>>>(x1);
    mma_gemm_kernel<128, true><<<GEMM_B, 256, SMEM128>>>(aggh, aggl, xh, xl, bt1, nullptr, h, 1);
    bn_finalize_kernel<<<1, 128>>>(gamma1, beta1, 1);
    bn_apply_kernel<<<APPLY_B, 256>>>(h, x1, x2);

    // ---- layer 2 ----
    aggregate_kernel<<<AGG_B, 256>>>(x2);
    mma_gemm_kernel<64, false><<<GEMM_B, 256, SMEM64>>>(aggh, aggl, xh, xl, bt2, b2, out, 0);
}

// round 5
// speedup vs baseline: 1.4750x; 1.2099x over previous
#include <cuda_runtime.h>
#include <cuda_bf16.h>
#include <cuda_fp16.h>
#include <cstdint>

#define N_NODES 50000
#define N_EDGES 800000
#define C 128
#define BN_EPS 1e-5f

// ================= PTX helpers (sm_100-safe: mma.sync / ldmatrix / cp.async) =================
__device__ __forceinline__ uint32_t smem_u32(const void* p) {
    uint32_t a;
    asm("{ .reg .u64 t; cvta.to.shared.u64 t, %1; cvt.u32.u64 %0, t; }" : "=r"(a) : "l"(p));
    return a;
}
__device__ __forceinline__ void cpa16(uint32_t dst, const void* src, uint32_t sz) {
    asm volatile("cp.async.cg.shared.global [%0], [%1], 16, %2;" :: "r"(dst), "l"(src), "r"(sz));
}
#define CP_COMMIT() asm volatile("cp.async.commit_group;" ::: "memory")
__device__ __forceinline__ void ldsm_x4(uint32_t* r, uint32_t a) {
    asm volatile("ldmatrix.sync.aligned.m8n8.x4.shared.b16 {%0,%1,%2,%3}, [%4];"
                 : "=r"(r[0]), "=r"(r[1]), "=r"(r[2]), "=r"(r[3]) : "r"(a));
}
__device__ __forceinline__ void ldsm_x2(uint32_t* r, uint32_t a) {
    asm volatile("ldmatrix.sync.aligned.m8n8.x2.shared.b16 {%0,%1}, [%2];"
                 : "=r"(r[0]), "=r"(r[1]) : "r"(a));
}
__device__ __forceinline__ void mma16816(float* d, const uint32_t* a, const uint32_t* b) {
    asm volatile(
        "mma.sync.aligned.m16n8k16.row.col.f32.bf16.bf16.f32 "
        "{%0,%1,%2,%3},{%4,%5,%6,%7},{%8,%9},{%0,%1,%2,%3};"
        : "+f"(d[0]), "+f"(d[1]), "+f"(d[2]), "+f"(d[3])
        : "r"(a[0]), "r"(a[1]), "r"(a[2]), "r"(a[3]), "r"(b[0]), "r"(b[1]));
}

// ================= scratch =================
__device__ __align__(16) int   g_off[N_NODES + 4];
__device__ __align__(16) int   g_cursor[N_NODES + 4];
__device__ int   g_srcs[N_EDGES];
__device__ float g_ws[N_EDGES];
__device__ float g_h[N_NODES * C];
__device__ __half g_xf[N_NODES * C];          // fp16 features (gather operand)
__device__ __nv_bfloat16 g_xh[N_NODES * C];   // bf16 hi (GEMM operand)
__device__ __nv_bfloat16 g_xl[N_NODES * C];   // bf16 lo
__device__ __nv_bfloat16 g_aggh[N_NODES * C];
__device__ __nv_bfloat16 g_aggl[N_NODES * C];
__device__ __nv_bfloat16 g_bt0[12 * 128 * 64];
__device__ __nv_bfloat16 g_bt1[12 * 128 * 64];
__device__ __nv_bfloat16 g_bt2[12 * 64 * 64];
__device__ float g_sum[2 * C];
__device__ float g_sumsq[2 * C];

// ================= helpers =================
__device__ __forceinline__ void split_store4(float4 v, __nv_bfloat16* ph, __nv_bfloat16* pl) {
    __nv_bfloat16 hx = __float2bfloat16_rn(v.x), hy = __float2bfloat16_rn(v.y),
                  hz = __float2bfloat16_rn(v.z), hw = __float2bfloat16_rn(v.w);
    __nv_bfloat16 lx = __float2bfloat16_rn(v.x - __bfloat162float(hx)),
                  ly = __float2bfloat16_rn(v.y - __bfloat162float(hy)),
                  lz = __float2bfloat16_rn(v.z - __bfloat162float(hz)),
                  lw = __float2bfloat16_rn(v.w - __bfloat162float(hw));
    __nv_bfloat162 h0 = __halves2bfloat162(hx, hy), h1 = __halves2bfloat162(hz, hw);
    __nv_bfloat162 l0 = __halves2bfloat162(lx, ly), l1 = __halves2bfloat162(lz, lw);
    *(uint2*)ph = make_uint2(*(uint32_t*)&h0, *(uint32_t*)&h1);
    *(uint2*)pl = make_uint2(*(uint32_t*)&l0, *(uint32_t*)&l1);
}
__device__ __forceinline__ void half_store4(float4 v, __half* pf) {
    __half2 a = __floats2half2_rn(v.x, v.y);
    __half2 b = __floats2half2_rn(v.z, v.w);
    *(uint2*)pf = make_uint2(*(uint32_t*)&a, *(uint32_t*)&b);
}
__device__ __forceinline__ float4 recon4(const __nv_bfloat16* ph, const __nv_bfloat16* pl) {
    uint2 hv = *(const uint2*)ph;
    uint2 lv = *(const uint2*)pl;
    __nv_bfloat162 h0 = *(__nv_bfloat162*)&hv.x, h1 = *(__nv_bfloat162*)&hv.y;
    __nv_bfloat162 l0 = *(__nv_bfloat162*)&lv.x, l1 = *(__nv_bfloat162*)&lv.y;
    float2 a = __bfloat1622float2(h0), b = __bfloat1622float2(h1);
    float2 c = __bfloat1622float2(l0), d = __bfloat1622float2(l1);
    return make_float4(a.x + c.x, a.y + c.y, b.x + d.x, b.y + d.y);
}
__device__ __forceinline__ float2 h2f2(uint32_t h) {
    return __half22float2(*(__half2*)&h);
}

// ================= setup: zero counters/stats + split input x =================
__global__ void setup_kernel(const float* __restrict__ x) {
    int i = blockIdx.x * blockDim.x + threadIdx.x;
    if (i <= N_NODES) g_off[i] = 0;
    if (i < 2 * C) { g_sum[i] = 0.f; g_sumsq[i] = 0.f; }
    if (i < N_NODES * (C / 4)) {
        float4 v = ((const float4*)x)[i];
        split_store4(v, g_xh + (size_t)i * 4, g_xl + (size_t)i * 4);
        half_store4(v, g_xf + (size_t)i * 4);
    }
}

__global__ void hist_kernel(const int* __restrict__ dst) {
    int e = blockIdx.x * blockDim.x + threadIdx.x;
    if (e < N_EDGES) atomicAdd(&g_off[dst[e]], 1);
}

// single-block scan, 4 elems/thread: counts -> exclusive offsets (+cursor copy)
__global__ void scan_kernel() {
    __shared__ int warp_sums[32];
    __shared__ int carry;
    const int tid = threadIdx.x;
    const int lane = tid & 31;
    const int wid = tid >> 5;
    if (tid == 0) carry = 0;
    __syncthreads();
    for (int base = 0; base < N_NODES; base += 4096) {
        int i0 = base + tid * 4;
        int v0 = 0, v1 = 0, v2 = 0, v3 = 0;
        if (i0 + 3 < N_NODES) {
            int4 t = *(const int4*)(g_off + i0);
            v0 = t.x; v1 = t.y; v2 = t.z; v3 = t.w;
        } else {
            if (i0 < N_NODES) v0 = g_off[i0];
            if (i0 + 1 < N_NODES) v1 = g_off[i0 + 1];
            if (i0 + 2 < N_NODES) v2 = g_off[i0 + 2];
            if (i0 + 3 < N_NODES) v3 = g_off[i0 + 3];
        }
        int t = v0 + v1 + v2 + v3;
        int x = t;
        #pragma unroll
        for (int s = 1; s < 32; s <<= 1) {
            int u = __shfl_up_sync(0xFFFFFFFFu, x, s);
            if (lane >= s) x += u;
        }
        if (lane == 31) warp_sums[wid] = x;
        __syncthreads();
        if (wid == 0) {
            int ws = warp_sums[lane];
            #pragma unroll
            for (int s = 1; s < 32; s <<= 1) {
                int u = __shfl_up_sync(0xFFFFFFFFu, ws, s);
                if (lane >= s) ws += u;
            }
            warp_sums[lane] = ws;
        }
        __syncthreads();
        int excl = carry + (wid ? warp_sums[wid - 1] : 0) + (x - t);
        int e0 = excl, e1 = excl + v0, e2 = e1 + v1, e3 = e2 + v2;
        if (i0 + 3 < N_NODES) {
            *(int4*)(g_off + i0) = make_int4(e0, e1, e2, e3);
            *(int4*)(g_cursor + i0) = make_int4(e0, e1, e2, e3);
        } else {
            if (i0 < N_NODES) { g_off[i0] = e0; g_cursor[i0] = e0; }
            if (i0 + 1 < N_NODES) { g_off[i0 + 1] = e1; g_cursor[i0 + 1] = e1; }
            if (i0 + 2 < N_NODES) { g_off[i0 + 2] = e2; g_cursor[i0 + 2] = e2; }
        }
        __syncthreads();
        if (tid == 0) carry += warp_sums[31];
        __syncthreads();
    }
    if (tid == 0) g_off[N_NODES] = carry;
}

__global__ void build_csr_kernel(const int* __restrict__ src,
                                 const int* __restrict__ dst,
                                 const float* __restrict__ w) {
    int e = blockIdx.x * blockDim.x + threadIdx.x;
    if (e < N_EDGES) {
        int d = dst[e];
        int p = atomicAdd(&g_cursor[d], 1);
        g_srcs[p] = src[e];
        g_ws[p] = w[e];
    }
}

// ================= B-tiles: all 3 layers in one kernel =================
// Per layer: 12 slices s = q*2 + khalf; q: 0..5 (path = q/3, lo = q%3==1)
// Slice layout: [NN rows(n)][64 cols(k)] bf16 dense.
template <int NN>
__device__ __forceinline__ void bt_fill(int idx, const float* Wrel, const float* Wroot,
                                        __nv_bfloat16* Bt) {
    int s = idx / (NN * 64);
    int r = idx % (NN * 64);
    int n = r / 64;
    int kk = r % 64;
    int q = s >> 1;
    int kh = s & 1;
    const float* W = (q < 3) ? Wrel : Wroot;
    bool lo = ((q % 3) == 1);
    float w = W[(size_t)(kh * 64 + kk) * NN + n];
    __nv_bfloat16 hv = __float2bfloat16_rn(w);
    Bt[(size_t)s * NN * 64 + n * 64 + kk] =
        lo ? __float2bfloat16_rn(w - __bfloat162float(hv)) : hv;
}
__global__ void build_bt_all(const float* __restrict__ Wr0, const float* __restrict__ Wo0,
                             const float* __restrict__ Wr1, const float* __restrict__ Wo1,
                             const float* __restrict__ Wr2, const float* __restrict__ Wo2) {
    int idx = blockIdx.x * 256 + threadIdx.x;
    const int B128 = 12 * 128 * 64;
    const int B64 = 12 * 64 * 64;
    if (idx < B128) bt_fill<128>(idx, Wr0, Wo0, g_bt0);
    else if (idx < 2 * B128) bt_fill<128>(idx - B128, Wr1, Wo1, g_bt1);
    else if (idx < 2 * B128 + B64) bt_fill<64>(idx - 2 * B128, Wr2, Wo2, g_bt2);
}

// ================= aggregation: one warp/node, fp16 gather, fp32 accum =================
__global__ void aggregate_kernel() {
    int gw = (blockIdx.x * blockDim.x + threadIdx.x) >> 5;
    int lane = threadIdx.x & 31;
    if (gw >= N_NODES) return;
    int j = g_off[gw];
    int e = g_off[gw + 1];
    float4 acc = make_float4(0.f, 0.f, 0.f, 0.f);
    const __half* xf = g_xf;
    for (; j + 3 < e; j += 4) {
        int s0 = g_srcs[j], s1 = g_srcs[j + 1], s2 = g_srcs[j + 2], s3 = g_srcs[j + 3];
        float w0 = g_ws[j], w1 = g_ws[j + 1], w2 = g_ws[j + 2], w3 = g_ws[j + 3];
        uint2 r0 = __ldg((const uint2*)(xf + (size_t)s0 * C) + lane);
        uint2 r1 = __ldg((const uint2*)(xf + (size_t)s1 * C) + lane);
        uint2 r2 = __ldg((const uint2*)(xf + (size_t)s2 * C) + lane);
        uint2 r3 = __ldg((const uint2*)(xf + (size_t)s3 * C) + lane);
        float2 a, b;
        a = h2f2(r0.x); b = h2f2(r0.y);
        acc.x = fmaf(w0, a.x, acc.x); acc.y = fmaf(w0, a.y, acc.y);
        acc.z = fmaf(w0, b.x, acc.z); acc.w = fmaf(w0, b.y, acc.w);
        a = h2f2(r1.x); b = h2f2(r1.y);
        acc.x = fmaf(w1, a.x, acc.x); acc.y = fmaf(w1, a.y, acc.y);
        acc.z = fmaf(w1, b.x, acc.z); acc.w = fmaf(w1, b.y, acc.w);
        a = h2f2(r2.x); b = h2f2(r2.y);
        acc.x = fmaf(w2, a.x, acc.x); acc.y = fmaf(w2, a.y, acc.y);
        acc.z = fmaf(w2, b.x, acc.z); acc.w = fmaf(w2, b.y, acc.w);
        a = h2f2(r3.x); b = h2f2(r3.y);
        acc.x = fmaf(w3, a.x, acc.x); acc.y = fmaf(w3, a.y, acc.y);
        acc.z = fmaf(w3, b.x, acc.z); acc.w = fmaf(w3, b.y, acc.w);
    }
    for (; j < e; j++) {
        int s = g_srcs[j];
        float w = g_ws[j];
        uint2 r = __ldg((const uint2*)(xf + (size_t)s * C) + lane);
        float2 a = h2f2(r.x), b = h2f2(r.y);
        acc.x = fmaf(w, a.x, acc.x); acc.y = fmaf(w, a.y, acc.y);
        acc.z = fmaf(w, b.x, acc.z); acc.w = fmaf(w, b.y, acc.w);
    }
    size_t base = (size_t)gw * C + lane * 4;
    split_store4(acc, g_aggh + base, g_aggl + base);
}

// ================= HMMA GEMM: H[128,NN] = agg@Wrel + x@Wroot (bf16x3) =================
template <int NN, bool STATS>
__global__ void __launch_bounds__(256) mma_gemm_kernel(
    const __nv_bfloat16* __restrict__ Ah, const __nv_bfloat16* __restrict__ Al,
    const __nv_bfloat16* __restrict__ Xh, const __nv_bfloat16* __restrict__ Xl,
    const __nv_bfloat16* __restrict__ Bt,
    const float* __restrict__ bias, float* __restrict__ H, int layer) {
    constexpr int WM = (NN == 128) ? 2 : 4;
    constexpr int WN = 8 / WM;
    constexpr int MF = 128 / (WM * 16);
    constexpr int NF = NN / (WN * 8);
    constexpr int PITCH = 144;
    constexpr int ABYTES = 128 * PITCH;
    constexpr int BBYTES = NN * PITCH;

    extern __shared__ __align__(16) char smem[];
    const uint32_t sb = smem_u32(smem);
    const uint32_t sA[2] = {sb, sb + ABYTES};
    const uint32_t sB[2] = {sb + 2 * ABYTES, sb + 2 * ABYTES + BBYTES};
    __shared__ float ssum[NN], ssq[NN];

    const int tid = threadIdx.x;
    const int wid = tid >> 5;
    const int lane = tid & 31;
    const int m0 = blockIdx.x * 128;
    const int wmb = (wid / WN) * (MF * 16);
    const int wnb = (wid % WN) * (NF * 8);

    const __nv_bfloat16* asrc[6] = {Ah, Ah, Al, Xh, Xh, Xl};

    float acc[MF][NF][4];
    #pragma unroll
    for (int i = 0; i < MF; i++)
        #pragma unroll
        for (int j = 0; j < NF; j++)
            #pragma unroll
            for (int k = 0; k < 4; k++) acc[i][j][k] = 0.f;

    auto load_tile = [&](int it) {
        int q = it >> 1, kh = it & 1, buf = it & 1;
        const __nv_bfloat16* As = asrc[q];
        #pragma unroll
        for (int u = 0; u < 4; u++) {
            int unit = tid + u * 256;
            int row = unit >> 3, cu = unit & 7;
            int m = m0 + row;
            cpa16(sA[buf] + row * PITCH + cu * 16,
                  (const char*)(As + (size_t)m * C + kh * 64) + cu * 16,
                  (m < N_NODES) ? 16u : 0u);
        }
        const char* Bs = (const char*)(Bt + (size_t)it * NN * 64);
        #pragma unroll
        for (int u = 0; u < NN / 32; u++) {
            int unit = tid + u * 256;
            int n = unit >> 3, cu = unit & 7;
            cpa16(sB[buf] + n * PITCH + cu * 16, Bs + n * 128 + cu * 16, 16u);
        }
    };

    const uint32_t a_lane = (lane & 7) * PITCH + ((lane >> 3) & 1) * 8 * PITCH + (lane >> 4) * 16;
    const uint32_t b_lane = (lane & 7) * PITCH + (((lane & 15) >> 3)) * 16;

    load_tile(0);
    CP_COMMIT();
    for (int it = 0; it < 12; it++) {
        if (it < 11) {
            load_tile(it + 1);
            CP_COMMIT();
            asm volatile("cp.async.wait_group 1;" ::: "memory");
        } else {
            asm volatile("cp.async.wait_group 0;" ::: "memory");
        }
        __syncthreads();
        uint32_t abase = sA[it & 1] + wmb * PITCH + a_lane;
        uint32_t bbase = sB[it & 1] + wnb * PITCH + b_lane;
        #pragma unroll
        for (int ks = 0; ks < 4; ks++) {
            uint32_t a[MF][4], b[NF][2];
            #pragma unroll
            for (int mf = 0; mf < MF; mf++) ldsm_x4(a[mf], abase + mf * 16 * PITCH + ks * 32);
            #pragma unroll
            for (int nf = 0; nf < NF; nf++) ldsm_x2(b[nf], bbase + nf * 8 * PITCH + ks * 32);
            #pragma unroll
            for (int mf = 0; mf < MF; mf++)
                #pragma unroll
                for (int nf = 0; nf < NF; nf++) mma16816(acc[mf][nf], a[mf], b[nf]);
        }
        __syncthreads();
    }

    if (STATS) {
        if (tid < NN) { ssum[tid] = 0.f; ssq[tid] = 0.f; }
        __syncthreads();
    }

    #pragma unroll
    for (int mf = 0; mf < MF; mf++) {
        int r = m0 + wmb + mf * 16 + (lane >> 2);
        #pragma unroll
        for (int nf = 0; nf < NF; nf++) {
            int cc = wnb + nf * 8 + (lane & 3) * 2;
            float b0 = bias ? bias[cc] : 0.f;
            float b1 = bias ? bias[cc + 1] : 0.f;
            if (r < N_NODES)
                *(float2*)(H + (size_t)r * NN + cc) =
                    make_float2(acc[mf][nf][0] + b0, acc[mf][nf][1] + b1);
            if (r + 8 < N_NODES)
                *(float2*)(H + (size_t)(r + 8) * NN + cc) =
                    make_float2(acc[mf][nf][2] + b0, acc[mf][nf][3] + b1);
        }
    }

    if (STATS) {
        #pragma unroll
        for (int nf = 0; nf < NF; nf++) {
            #pragma unroll
            for (int j = 0; j < 2; j++) {
                int col = wnb + nf * 8 + (lane & 3) * 2 + j;
                float s = 0.f, q = 0.f;
                #pragma unroll
                for (int mf = 0; mf < MF; mf++) {
                    float v0 = acc[mf][nf][j];
                    float v1 = acc[mf][nf][2 + j];
                    s += v0 + v1;
                    q += v0 * v0 + v1 * v1;
                }
                atomicAdd(&ssum[col], s);
                atomicAdd(&ssq[col], q);
            }
        }
        __syncthreads();
        if (tid < NN) {
            atomicAdd(&g_sum[layer * C + tid], ssum[tid]);
            atomicAdd(&g_sumsq[layer * C + tid], ssq[tid]);
        }
    }
}

// ================= BN apply (finalize fused): in-place feature update =================
// o = relu(h*scale + shift + residual); residual from bf16 pair; writes xf/xh/xl.
__global__ void bn_apply_kernel(const float* __restrict__ h,
                                const float* __restrict__ gamma,
                                const float* __restrict__ beta, int layer) {
    int i = blockIdx.x * blockDim.x + threadIdx.x;
    if (i >= N_NODES * (C / 4)) return;
    int c = (i & 31) << 2;
    float4 sm = *(const float4*)(g_sum + layer * C + c);
    float4 sq = *(const float4*)(g_sumsq + layer * C + c);
    float4 gm = *(const float4*)(gamma + c);
    float4 bt = *(const float4*)(beta + c);
    const float inv = 1.f / N_NODES;
    float mx = sm.x * inv, my = sm.y * inv, mz = sm.z * inv, mw = sm.w * inv;
    float scx = gm.x * rsqrtf(sq.x * inv - mx * mx + BN_EPS);
    float scy = gm.y * rsqrtf(sq.y * inv - my * my + BN_EPS);
    float scz = gm.z * rsqrtf(sq.z * inv - mz * mz + BN_EPS);
    float scw = gm.w * rsqrtf(sq.w * inv - mw * mw + BN_EPS);
    float shx = bt.x - mx * scx, shy = bt.y - my * scy;
    float shz = bt.z - mz * scz, shw = bt.w - mw * scw;

    float4 hv = ((const float4*)h)[i];
    float4 xv = recon4(g_xh + (size_t)i * 4, g_xl + (size_t)i * 4);
    float4 o;
    o.x = fmaxf(fmaf(hv.x, scx, shx) + xv.x, 0.f);
    o.y = fmaxf(fmaf(hv.y, scy, shy) + xv.y, 0.f);
    o.z = fmaxf(fmaf(hv.z, scz, shz) + xv.z, 0.f);
    o.w = fmaxf(fmaf(hv.w, scw, shw) + xv.w, 0.f);
    split_store4(o, g_xh + (size_t)i * 4, g_xl + (size_t)i * 4);
    half_store4(o, g_xf + (size_t)i * 4);
}

// ================= launch =================
extern "C" void kernel_launch(void* const* d_in, const int* in_sizes, int n_in,
                              void* d_out, int out_size) {
    const float* x    = (const float*)d_in[0];
    const int*   esrc = (const int*)d_in[1];
    const int*   edst = (const int*)d_in[2];
    const float* ew   = (const float*)d_in[3];
    const float* Wr0  = (const float*)d_in[4];
    // b_rel0 (d_in[5]) cancels exactly under BN
    const float* Wo0  = (const float*)d_in[6];
    const float* Wr1  = (const float*)d_in[7];
    // b_rel1 (d_in[8]) cancels under BN
    const float* Wo1  = (const float*)d_in[9];
    const float* Wr2  = (const float*)d_in[10];
    const float* b2   = (const float*)d_in[11];
    const float* Wo2  = (const float*)d_in[12];
    const float* gamma0 = (const float*)d_in[13];
    const float* beta0  = (const float*)d_in[14];
    const float* gamma1 = (const float*)d_in[15];
    const float* beta1  = (const float*)d_in[16];
    float* out = (float*)d_out;

    float* h;
    __nv_bfloat16 *aggh, *aggl, *xh, *xl, *bt0, *bt1, *bt2;
    cudaGetSymbolAddress((void**)&h, g_h);
    cudaGetSymbolAddress((void**)&aggh, g_aggh);
    cudaGetSymbolAddress((void**)&aggl, g_aggl);
    cudaGetSymbolAddress((void**)&xh, g_xh);
    cudaGetSymbolAddress((void**)&xl, g_xl);
    cudaGetSymbolAddress((void**)&bt0, g_bt0);
    cudaGetSymbolAddress((void**)&bt1, g_bt1);
    cudaGetSymbolAddress((void**)&bt2, g_bt2);

    const int SMEM128 = 2 * 128 * 144 + 2 * 128 * 144;  // 73728
    const int SMEM64  = 2 * 128 * 144 + 2 * 64 * 144;   // 55296
    cudaFuncSetAttribute(mma_gemm_kernel<128, true>,
                         cudaFuncAttributeMaxDynamicSharedMemorySize, SMEM128);
    cudaFuncSetAttribute(mma_gemm_kernel<64, false>,
                         cudaFuncAttributeMaxDynamicSharedMemorySize, SMEM64);

    const int EB = (N_EDGES + 255) / 256;
    const int AGG_B = (N_NODES + 7) / 8;
    const int GEMM_B = (N_NODES + 127) / 128;
    const int APPLY_B = (N_NODES * (C / 4) + 255) / 256;  // 6250
    const int BT_TOTAL = 2 * (12 * 128 * 64) + 12 * 64 * 64;

    setup_kernel<<<APPLY_B, 256>>>(x);
    hist_kernel<<<EB, 256>>>(edst);
    scan_kernel<<<1, 1024>>>();
    build_csr_kernel<<<EB, 256>>>(esrc, edst, ew);
    build_bt_all<<<(BT_TOTAL + 255) / 256, 256>>>(Wr0, Wo0, Wr1, Wo1, Wr2, Wo2);

    // ---- layer 0 ----
    aggregate_kernel<<<AGG_B, 256>>>();
    mma_gemm_kernel<128, true><<<GEMM_B, 256, SMEM128>>>(aggh, aggl, xh, xl, bt0, nullptr, h, 0);
    bn_apply_kernel<<<APPLY_B, 256>>>(h, gamma0, beta0, 0);

    // ---- layer 1 ----
    aggregate_kernel<<<AGG_B, 256>>>();
    mma_gemm_kernel<128, true><<<GEMM_B, 256, SMEM128>>>(aggh, aggl, xh, xl, bt1, nullptr, h, 1);
    bn_apply_kernel<<<APPLY_B, 256>>>(h, gamma1, beta1, 1);

    // ---- layer 2 ----
    aggregate_kernel<<<AGG_B, 256>>>();
    mma_gemm_kernel<64, false><<<GEMM_B, 256, SMEM64>>>(aggh, aggl, xh, xl, bt2, b2, out, 0);
}